// round 8
// baseline (speedup 1.0000x reference)
#include <cuda_runtime.h>
#include <math.h>

#define BB 16
#define S_PAST 4096
#define S_TOT 4097
#define DD 1024
#define HH 16
#define HDI 64
#define CHUNK 108    // 38*16 = 608 CTAs = 2 full waves on 152 SMs @ occ 2
#define NCH 38
#define RPB 4        // rows per pipeline batch (16 KB)
#define NST 6        // pipeline stages
#define LOOKAHEAD 3
#define ROW_BYTES (DD * 4)
#define STAGE_BYTES (RPB * ROW_BYTES)

// ---------------- scratch (static device globals; no allocation) ----------------
__device__ __align__(16) float g_q[BB * DD];
__device__ __align__(16) float g_qkt[BB * HH * DD];
__device__ float g_qbk[BB * HH];
__device__ __align__(16) float2 g_ms[BB * NCH * HH];
__device__ __align__(16) float g_partial[(size_t)BB * NCH * HH * DD];
__device__ __align__(16) float g_wsum[BB * HH * DD];
__device__ __align__(16) float g_ctx[BB * DD];

// ---------------- packed f32x2 helpers ----------------
__device__ __forceinline__ void ffma2(unsigned long long& d, unsigned long long a,
                                      unsigned long long b) {
    asm("fma.rn.f32x2 %0, %1, %2, %0;" : "+l"(d) : "l"(a), "l"(b));
}
union U64F2 { unsigned long long u; float2 f; };
__device__ __forceinline__ float hadd2(unsigned long long a) {
    U64F2 t; t.u = a; return t.f.x + t.f.y;
}
__device__ __forceinline__ unsigned long long dup2(float x) {
    unsigned long long r;
    asm("mov.b64 %0, {%1, %1};" : "=l"(r) : "r"(__float_as_uint(x)));
    return r;
}

// ---------------- TMA / mbarrier helpers ----------------
__device__ __forceinline__ unsigned smem_u32(const void* p) {
    unsigned a;
    asm("{ .reg .u64 t; cvta.to.shared.u64 t, %1; cvt.u32.u64 %0, t; }" : "=r"(a) : "l"(p));
    return a;
}
__device__ __forceinline__ void mbar_init(unsigned a, unsigned cnt) {
    asm volatile("mbarrier.init.shared.b64 [%0], %1;" :: "r"(a), "r"(cnt) : "memory");
}
__device__ __forceinline__ void mbar_expect_tx(unsigned a, unsigned bytes) {
    asm volatile("mbarrier.arrive.expect_tx.shared.b64 _, [%0], %1;" :: "r"(a), "r"(bytes) : "memory");
}
__device__ __forceinline__ void mbar_wait(unsigned a, unsigned ph) {
    asm volatile(
        "{\n\t.reg .pred P;\n"
        "W0_%=:\n\t"
        "mbarrier.try_wait.parity.acquire.cta.shared::cta.b64 P, [%0], %1, 0x989680;\n\t"
        "@P bra W1_%=;\n\t"
        "bra W0_%=;\n"
        "W1_%=:\n\t}"
        :: "r"(a), "r"(ph) : "memory");
}
__device__ __forceinline__ void bulk_g2s(unsigned dst, const float* src, unsigned bytes, unsigned mbar) {
    asm volatile("cp.async.bulk.shared::cluster.global.mbarrier::complete_tx::bytes [%0], [%1], %2, [%3];"
                 :: "r"(dst), "l"(src), "r"(bytes), "r"(mbar) : "memory");
}
__device__ __forceinline__ void bulk_s2g(float* dst, unsigned src, unsigned bytes) {
    asm volatile("cp.async.bulk.global.shared::cta.bulk_group [%0], [%1], %2;"
                 :: "l"(dst), "r"(src), "r"(bytes) : "memory");
}
__device__ __forceinline__ void bulk_commit() {
    asm volatile("cp.async.bulk.commit_group;" ::: "memory");
}
template <int N>
__device__ __forceinline__ void bulk_wait_read() {
    asm volatile("cp.async.bulk.wait_group.read %0;" :: "n"(N) : "memory");
}
__device__ __forceinline__ void bulk_wait_all() {
    asm volatile("cp.async.bulk.wait_group 0;" ::: "memory");
}

// ---------------------------------------------------------------------------
// Batch-amortized GEMV core: block handles 16 weight rows x all 16 batches.
// Activations (16 x 1024 f32 = 64KB) live in dynamic SMEM; each weight row is
// read ONCE; each warp computes 2 rows simultaneously (halves LDS traffic).
__device__ __forceinline__ void gemv16(const float* __restrict__ wmat, size_t wrow0,
                                       const float* __restrict__ bias, int bias_off,
                                       float* __restrict__ dstbase, int obase,
                                       float scale, const float4* cxs /*smem*/) {
    int t = threadIdx.x, w = t >> 5, l = t & 31;
    int o0 = obase + w * 2, o1 = o0 + 1;
    const float4* wr0 = (const float4*)(wmat + (wrow0 + o0 - obase + obase) * (size_t)DD);
    // note: wrow0 already includes obase offset externally; recompute cleanly:
    wr0 = (const float4*)(wmat + (size_t)(wrow0 + w * 2) * DD);
    const float4* wr1 = wr0 + 256;
    float acc0[BB], acc1[BB];
#pragma unroll
    for (int b = 0; b < BB; b++) { acc0[b] = 0.f; acc1[b] = 0.f; }
#pragma unroll
    for (int i = 0; i < 8; i++) {
        float4 y0 = wr0[l + 32 * i];
        float4 y1 = wr1[l + 32 * i];
#pragma unroll
        for (int b = 0; b < BB; b++) {
            float4 x = cxs[b * 256 + l + 32 * i];
            acc0[b] += x.x * y0.x + x.y * y0.y + x.z * y0.z + x.w * y0.w;
            acc1[b] += x.x * y1.x + x.y * y1.y + x.z * y1.z + x.w * y1.w;
        }
    }
#pragma unroll
    for (int b = 0; b < BB; b++) {
#pragma unroll
        for (int off = 16; off; off >>= 1) {
            acc0[b] += __shfl_xor_sync(~0u, acc0[b], off);
            acc1[b] += __shfl_xor_sync(~0u, acc1[b], off);
        }
    }
    if (l == 0) {
        float bb0 = bias[bias_off + o0], bb1 = bias[bias_off + o1];
#pragma unroll
        for (int b = 0; b < BB; b++) {
            dstbase[(size_t)b * DD + o0] = (acc0[b] + bb0) * scale;
            dstbase[(size_t)b * DD + o1] = (acc1[b] + bb1) * scale;
        }
    }
}

// K1: q projection, batch-amortized. grid 64, block 256, dyn smem 64KB.
__global__ void __launch_bounds__(256) k_qp(const float* __restrict__ query,
                                            const float* __restrict__ w_in,
                                            const float* __restrict__ b_in) {
    extern __shared__ __align__(16) float4 cxs[];  // [16][256]
    int t = threadIdx.x;
    for (int i = t; i < BB * 256; i += 256) cxs[i] = ((const float4*)query)[i];
    __syncthreads();
    int obase = blockIdx.x * 16;
    gemv16(w_in, obase, b_in, 0, g_q, obase, 0.125f, cxs);
}

// K2: fold q into per-head K weights. grid (HH, 2), block 256.
// qkt[b,h,:] = sum_j q[b,64h+j] * w_in[D+64h+j,:]; qbk[b,h] = q_h . bk_h.
__global__ void __launch_bounds__(256) k_fold(const float* __restrict__ w_in,
                                              const float* __restrict__ b_in) {
    int h = blockIdx.x, b0 = blockIdx.y * 8;
    int t = threadIdx.x;
    __shared__ float qs[8][HDI];
    for (int i = t; i < 8 * HDI; i += 256)
        qs[i >> 6][i & 63] = g_q[(size_t)(b0 + (i >> 6)) * DD + h * HDI + (i & 63)];
    __syncthreads();
    if (t < 8) {
        float s = 0.f;
        for (int j = 0; j < HDI; j++) s += qs[t][j] * b_in[DD + h * HDI + j];
        g_qbk[(b0 + t) * HH + h] = s;
    }
    float4 acc[8];
#pragma unroll
    for (int b = 0; b < 8; b++) acc[b] = make_float4(0.f, 0.f, 0.f, 0.f);
    const float4* wk4 = (const float4*)(w_in + (size_t)(DD + h * HDI) * DD);
#pragma unroll 4
    for (int j = 0; j < HDI; j++) {
        float4 wv = wk4[(size_t)j * 256 + t];
#pragma unroll
        for (int b = 0; b < 8; b++) {
            float qv = qs[b][j];
            acc[b].x += qv * wv.x; acc[b].y += qv * wv.y;
            acc[b].z += qv * wv.z; acc[b].w += qv * wv.w;
        }
    }
#pragma unroll
    for (int b = 0; b < 8; b++)
        ((float4*)g_qkt)[(size_t)((b0 + b) * HH + h) * 256 + t] = acc[b];
}

// ---------------------------------------------------------------------------
// K3: fused streaming kernel (unchanged from round 7 winner).
struct BInfo { const float* src; float* dst; int rows; };

__device__ __forceinline__ BInfo binfo(int j, int nbt1, int s0, int nrows, int b,
                                       const float* pk, const float* ky,
                                       const float* pv, const float* vl,
                                       float* ck, float* cv) {
    BInfo r;
    int isV = (j >= nbt1);
    int lb = isV ? j - nbt1 : j;
    int s_abs = s0 + lb * RPB;
    r.rows = min(RPB, nrows - lb * RPB);
    const float* past = isV ? pv : pk;
    const float* cur  = isV ? vl : ky;
    r.src = (s_abs < S_PAST) ? past + ((size_t)b * S_PAST + s_abs) * DD
                             : cur + (size_t)b * DD;
    r.dst = (isV ? cv : ck) + ((size_t)b * S_TOT + s_abs) * DD;
    return r;
}

__global__ void __launch_bounds__(256, 2) k_main(const float* __restrict__ past_key,
                                                 const float* __restrict__ key,
                                                 const float* __restrict__ past_value,
                                                 const float* __restrict__ value,
                                                 float* __restrict__ comb_key,
                                                 float* __restrict__ comb_value) {
    extern __shared__ __align__(128) float4 sbuf[];   // NST*STAGE_BYTES = 96KB
    __shared__ __align__(8) unsigned long long mbar_st[NST];
    __shared__ float sc[HH * CHUNK];
    int chunk = blockIdx.x, b = blockIdx.y;
    int t = threadIdx.x, w = t >> 5, l = t & 31;
    int s0 = chunk * CHUNK;
    int nrows = min(CHUNK, S_TOT - s0);
    int nbt1 = (nrows + RPB - 1) / RPB;
    int ntot = 2 * nbt1;

    unsigned sbase = smem_u32(sbuf);
    unsigned mb0 = smem_u32(&mbar_st[0]);

    if (t == 0) {
        for (int i = 0; i < NST; i++) mbar_init(mb0 + 8 * i, 1);
    }
    __syncthreads();
    if (t == 0) {
        for (int i = 0; i < LOOKAHEAD && i < ntot; i++) {
            BInfo bi = binfo(i, nbt1, s0, nrows, b, past_key, key, past_value, value,
                             comb_key, comb_value);
            unsigned bytes = bi.rows * ROW_BYTES;
            mbar_expect_tx(mb0 + 8 * i, bytes);
            bulk_g2s(sbase + i * STAGE_BYTES, bi.src, bytes, mb0 + 8 * i);
        }
    }

    // ---- K phase ----
    {
        int h0 = 2 * w, h1 = h0 + 1;
        ulonglong2 q0[8], q1[8];
        const ulonglong2* qk0 = (const ulonglong2*)(g_qkt + (size_t)(b * HH + h0) * DD);
        const ulonglong2* qk1 = (const ulonglong2*)(g_qkt + (size_t)(b * HH + h1) * DD);
#pragma unroll
        for (int i = 0; i < 8; i++) { q0[i] = qk0[l + 32 * i]; q1[i] = qk1[l + 32 * i]; }
        float qb0 = g_qbk[b * HH + h0], qb1 = g_qbk[b * HH + h1];

        for (int bt = 0; bt < nbt1; bt++) {
            int st = bt % NST;
            unsigned ph = (bt / NST) & 1;
            BInfo bi = binfo(bt, nbt1, s0, nrows, b, past_key, key, past_value, value,
                             comb_key, comb_value);
            mbar_wait(mb0 + 8 * st, ph);
            if (t == 0) {
                bulk_s2g(bi.dst, sbase + st * STAGE_BYTES, bi.rows * ROW_BYTES);
                bulk_commit();
            }
            const ulonglong2* stg = (const ulonglong2*)(sbuf + st * (RPB * 256));
#pragma unroll
            for (int r = 0; r < RPB; r++) {
                if (r >= bi.rows) break;
                const ulonglong2* rb = stg + r * 256;
                unsigned long long a0a = 0ull, a0b = 0ull, a1a = 0ull, a1b = 0ull;
#pragma unroll
                for (int i = 0; i < 8; i++) {
                    ulonglong2 x = rb[l + 32 * i];
                    ffma2(a0a, x.x, q0[i].x); ffma2(a0b, x.y, q0[i].y);
                    ffma2(a1a, x.x, q1[i].x); ffma2(a1b, x.y, q1[i].y);
                }
                float f0 = hadd2(a0a) + hadd2(a0b);
                float f1 = hadd2(a1a) + hadd2(a1b);
#pragma unroll
                for (int off = 16; off; off >>= 1) {
                    f0 += __shfl_xor_sync(~0u, f0, off);
                    f1 += __shfl_xor_sync(~0u, f1, off);
                }
                int sl = bt * RPB + r;
                if (l == 0) sc[h0 * CHUNK + sl] = f0 + qb0;
                if (l == 1) sc[h1 * CHUNK + sl] = f1 + qb1;
            }
            __syncthreads();
            if (t == 0 && bt + LOOKAHEAD < ntot) {
                int nb = bt + LOOKAHEAD;
                BInfo nbi = binfo(nb, nbt1, s0, nrows, b, past_key, key, past_value, value,
                                  comb_key, comb_value);
                unsigned bytes = nbi.rows * ROW_BYTES;
                bulk_wait_read<LOOKAHEAD>();
                mbar_expect_tx(mb0 + 8 * (nb % NST), bytes);
                bulk_g2s(sbase + (nb % NST) * STAGE_BYTES, nbi.src, bytes, mb0 + 8 * (nb % NST));
            }
        }
    }

    // ---- local split-softmax ----
    {
#pragma unroll
        for (int hh = 2 * w; hh <= 2 * w + 1; hh++) {
            float* row = sc + hh * CHUNK;
            float m = -1e30f;
            for (int i = l; i < nrows; i += 32) m = fmaxf(m, row[i]);
#pragma unroll
            for (int off = 16; off; off >>= 1) m = fmaxf(m, __shfl_xor_sync(~0u, m, off));
            float s = 0.f;
            for (int i = l; i < nrows; i += 32) {
                float e = expf(row[i] - m);
                row[i] = e;
                s += e;
            }
#pragma unroll
            for (int off = 16; off; off >>= 1) s += __shfl_xor_sync(~0u, s, off);
            if (l == 0) g_ms[(size_t)(b * NCH + chunk) * HH + hh] = make_float2(m, s);
        }
        __syncthreads();
    }

    // ---- V phase ----
    {
        unsigned long long acc[HH][2];
#pragma unroll
        for (int h = 0; h < HH; h++) { acc[h][0] = 0ull; acc[h][1] = 0ull; }

        for (int bt = nbt1; bt < ntot; bt++) {
            int st = bt % NST;
            unsigned ph = (bt / NST) & 1;
            int lb = bt - nbt1;
            BInfo bi = binfo(bt, nbt1, s0, nrows, b, past_key, key, past_value, value,
                             comb_key, comb_value);
            mbar_wait(mb0 + 8 * st, ph);
            if (t == 0) {
                bulk_s2g(bi.dst, sbase + st * STAGE_BYTES, bi.rows * ROW_BYTES);
                bulk_commit();
            }
            const ulonglong2* stg = (const ulonglong2*)(sbuf + st * (RPB * 256));
#pragma unroll
            for (int r = 0; r < RPB; r++) {
                if (r >= bi.rows) break;
                ulonglong2 cur = stg[r * 256 + t];
                const float* ar = sc + lb * RPB + r;
#pragma unroll
                for (int h = 0; h < HH; h++) {
                    unsigned long long a2 = dup2(ar[h * CHUNK]);
                    ffma2(acc[h][0], a2, cur.x);
                    ffma2(acc[h][1], a2, cur.y);
                }
            }
            __syncthreads();
            if (t == 0 && bt + LOOKAHEAD < ntot) {
                int nb = bt + LOOKAHEAD;
                BInfo nbi = binfo(nb, nbt1, s0, nrows, b, past_key, key, past_value, value,
                                  comb_key, comb_value);
                unsigned bytes = nbi.rows * ROW_BYTES;
                bulk_wait_read<LOOKAHEAD>();
                mbar_expect_tx(mb0 + 8 * (nb % NST), bytes);
                bulk_g2s(sbase + (nb % NST) * STAGE_BYTES, nbi.src, bytes, mb0 + 8 * (nb % NST));
            }
        }

        ulonglong2* part = (ulonglong2*)(g_partial + (size_t)(b * NCH + chunk) * HH * DD);
#pragma unroll
        for (int h = 0; h < HH; h++)
            part[(size_t)h * 256 + t] = make_ulonglong2(acc[h][0], acc[h][1]);
    }
    if (t == 0) bulk_wait_all();
}

// ---------------------------------------------------------------------------
// K4: split-softmax combine + partial reduce -> g_wsum. grid (HH, BB).
__global__ void __launch_bounds__(256) k_red() {
    int h = blockIdx.x, b = blockIdx.y;
    int t = threadIdx.x;
    __shared__ float scl[NCH];
    if (t == 0) {
        float M = -1e30f;
        for (int c = 0; c < NCH; c++)
            M = fmaxf(M, g_ms[(size_t)(b * NCH + c) * HH + h].x);
        float S = 0.f;
        for (int c = 0; c < NCH; c++) {
            float2 ms = g_ms[(size_t)(b * NCH + c) * HH + h];
            S += expf(ms.x - M) * ms.y;
        }
        float invS = 1.f / S;
        for (int c = 0; c < NCH; c++)
            scl[c] = expf(g_ms[(size_t)(b * NCH + c) * HH + h].x - M) * invS;
    }
    __syncthreads();
    float4 acc = make_float4(0.f, 0.f, 0.f, 0.f);
#pragma unroll 2
    for (int c = 0; c < NCH; c++) {
        float s = scl[c];
        float4 p = ((const float4*)g_partial)[((size_t)(b * NCH + c) * HH + h) * 256 + t];
        acc.x += s * p.x; acc.y += s * p.y; acc.z += s * p.z; acc.w += s * p.w;
    }
    ((float4*)g_wsum)[(size_t)(b * HH + h) * 256 + t] = acc;
}

// K5: ctx projection, batch-amortized. grid 64, block 256, dyn smem 64KB.
__global__ void __launch_bounds__(256) k_ctx(const float* __restrict__ w_in,
                                             const float* __restrict__ b_in) {
    extern __shared__ __align__(16) float4 cxs[];  // [16][256] of head h
    int t = threadIdx.x;
    int obase = blockIdx.x * 16;
    int h = obase >> 6;
    for (int i = t; i < BB * 256; i += 256) {
        int b = i >> 8, q = i & 255;
        cxs[i] = ((const float4*)g_wsum)[(size_t)(b * HH + h) * 256 + q];
    }
    __syncthreads();
    gemv16(w_in, (size_t)2 * DD + obase, b_in, 2 * DD, g_ctx, obase, 1.f, cxs);
}

// K6: output projection, batch-amortized. grid 64, block 256, dyn smem 64KB.
__global__ void __launch_bounds__(256) k_out(const float* __restrict__ w_out,
                                             const float* __restrict__ b_out,
                                             float* __restrict__ out) {
    extern __shared__ __align__(16) float4 cxs[];
    int t = threadIdx.x;
    for (int i = t; i < BB * 256; i += 256) cxs[i] = ((const float4*)g_ctx)[i];
    __syncthreads();
    int obase = blockIdx.x * 16;
    gemv16(w_out, obase, b_out, 0, out, obase, 1.f, cxs);
}

// ---------------------------------------------------------------------------
extern "C" void kernel_launch(void* const* d_in, const int* in_sizes, int n_in,
                              void* d_out, int out_size) {
    const float* query      = (const float*)d_in[0];
    const float* key        = (const float*)d_in[1];
    const float* value      = (const float*)d_in[2];
    const float* past_key   = (const float*)d_in[3];
    const float* past_value = (const float*)d_in[4];
    const float* w_in       = (const float*)d_in[5];
    const float* b_in       = (const float*)d_in[6];
    const float* w_out      = (const float*)d_in[7];
    const float* b_out      = (const float*)d_in[8];

    float* out        = (float*)d_out;
    float* comb_key   = out + (size_t)BB * DD;
    float* comb_value = comb_key + (size_t)BB * S_TOT * DD;

    const int pipe_smem = NST * STAGE_BYTES;        // 96 KB
    const int gemv_smem = BB * DD * (int)sizeof(float);  // 64 KB
    cudaFuncSetAttribute(k_main, cudaFuncAttributeMaxDynamicSharedMemorySize, pipe_smem);
    cudaFuncSetAttribute(k_qp,   cudaFuncAttributeMaxDynamicSharedMemorySize, gemv_smem);
    cudaFuncSetAttribute(k_ctx,  cudaFuncAttributeMaxDynamicSharedMemorySize, gemv_smem);
    cudaFuncSetAttribute(k_out,  cudaFuncAttributeMaxDynamicSharedMemorySize, gemv_smem);

    k_qp  <<<64, 256, gemv_smem>>>(query, w_in, b_in);
    k_fold<<<dim3(HH, 2), 256>>>(w_in, b_in);
    k_main<<<dim3(NCH, BB), 256, pipe_smem>>>(past_key, key, past_value, value,
                                              comb_key, comb_value);
    k_red <<<dim3(HH, BB), 256>>>();
    k_ctx <<<64, 256, gemv_smem>>>(w_in, b_in);
    k_out <<<64, 256, gemv_smem>>>(w_out, b_out, out);
}